// round 10
// baseline (speedup 1.0000x reference)
#include <cuda_runtime.h>
#include <cuda_bf16.h>
#include <cstdint>
#include <math.h>

#define NEGV 1000000000000.0f

// ---------------- scratch (static device globals; no allocs) ----------------
__device__ float g_hp[8 * 4096 * 128];   // K-split partial h (8 splits)
__device__ __align__(16) unsigned char g_w1b[768 * 128 * 2];  // W1 bf16 row-major
__device__ float g_qT[4 * 64 * 1024];    // rope'd q, TRANSPOSED [b][d][m], pre-scaled 1/8
__device__ float g_kT[4 * 64 * 1024];    // rope'd k, TRANSPOSED [b][d][n]
__device__ float g_bA[4 * 16 * 1024];    // bias[b, n, 2o]/2   -> indexed [b][o][n]
__device__ float g_bB[4 * 16 * 1024];    // bias[b, m, 2o+1]/2 -> indexed [b][o][m]

// ---------------- packed f32x2 helpers ----------------
__device__ __forceinline__ unsigned long long pk2(float lo, float hi) {
    unsigned long long r;
    asm("mov.b64 %0, {%1,%2};" : "=l"(r) : "f"(lo), "f"(hi));
    return r;
}
__device__ __forceinline__ void fma2(unsigned long long& d, unsigned long long a,
                                     unsigned long long b) {
    asm("fma.rn.f32x2 %0, %1, %2, %0;" : "+l"(d) : "l"(a), "l"(b));
}
__device__ __forceinline__ unsigned long long fma2n(unsigned long long a,
                                                    unsigned long long b,
                                                    unsigned long long c) {
    unsigned long long d;
    asm("fma.rn.f32x2 %0, %1, %2, %3;" : "=l"(d) : "l"(a), "l"(b), "l"(c));
    return d;
}
__device__ __forceinline__ unsigned long long add2(unsigned long long a,
                                                   unsigned long long b) {
    unsigned long long d;
    asm("add.rn.f32x2 %0, %1, %2;" : "=l"(d) : "l"(a), "l"(b));
    return d;
}
__device__ __forceinline__ float2 up2(unsigned long long v) {
    float2 r;
    asm("mov.b64 {%0,%1}, %2;" : "=f"(r.x), "=f"(r.y) : "l"(v));
    return r;
}
__device__ __forceinline__ void cp_async16(void* smem_dst, const void* gsrc) {
    unsigned saddr = (unsigned)__cvta_generic_to_shared(smem_dst);
    asm volatile("cp.async.ca.shared.global [%0], [%1], 16;\n"
                 :: "r"(saddr), "l"(gsrc) : "memory");
}
__device__ __forceinline__ uint32_t packbf2(float a, float b) {
    __nv_bfloat162 v = __floats2bfloat162_rn(a, b);
    return *(uint32_t*)&v;
}
__device__ __forceinline__ void ldsm_x4(uint32_t& r0, uint32_t& r1, uint32_t& r2,
                                        uint32_t& r3, uint32_t addr) {
    asm volatile("ldmatrix.sync.aligned.m8n8.x4.shared.b16 {%0,%1,%2,%3}, [%4];"
                 : "=r"(r0), "=r"(r1), "=r"(r2), "=r"(r3) : "r"(addr));
}
__device__ __forceinline__ void ldsm_x4t(uint32_t& r0, uint32_t& r1, uint32_t& r2,
                                         uint32_t& r3, uint32_t addr) {
    asm volatile("ldmatrix.sync.aligned.m8n8.x4.trans.shared.b16 {%0,%1,%2,%3}, [%4];"
                 : "=r"(r0), "=r"(r1), "=r"(r2), "=r"(r3) : "r"(addr));
}
__device__ __forceinline__ void mma_bf16(float* d, uint32_t a0, uint32_t a1,
                                         uint32_t a2, uint32_t a3, uint32_t b0,
                                         uint32_t b1) {
    asm volatile(
        "mma.sync.aligned.m16n8k16.row.col.f32.bf16.bf16.f32 "
        "{%0,%1,%2,%3}, {%4,%5,%6,%7}, {%8,%9}, {%0,%1,%2,%3};"
        : "+f"(d[0]), "+f"(d[1]), "+f"(d[2]), "+f"(d[3])
        : "r"(a0), "r"(a1), "r"(a2), "r"(a3), "r"(b0), "r"(b1));
}

// ---------------- prep: W1 -> bf16 row-major ----------------
__global__ __launch_bounds__(256) void prep_w1_kernel(const float* __restrict__ W1) {
    int i = (blockIdx.x * 256 + threadIdx.x) * 4;   // 98304 elements
    float4 v = *(const float4*)(W1 + i);
    uint2 p;
    p.x = packbf2(v.x, v.y);
    p.y = packbf2(v.z, v.w);
    *(uint2*)(g_w1b + (size_t)i * 2) = p;
}

// ---------------- kernel 1a: h_partial = x@W1 via mma.sync bf16 -------------
// Grid: dim3(8 ksplit, 128 mblocks), 128 thr (4 warps).
// BM=32, BN=128 (full), K=96 per split (6 k16-steps).
// smem: A bf16 [32 rows][256B] swizzled @0 (8KB); B bf16 [96 rows][256B] @8192 (24KB).
// 32KB smem -> ~7 blocks/SM resident.
__global__ __launch_bounds__(128) void k1a_kernel(const float* __restrict__ x) {
    __shared__ __align__(16) unsigned char smem[32768];
    const uint32_t sbase = (uint32_t)__cvta_generic_to_shared(smem);
    const int tid = threadIdx.x;
    const int lane = tid & 31;
    const int warp = tid >> 5;
    const int ks = blockIdx.x;          // 0..7
    const int row0 = blockIdx.y * 32;
    const int k0 = ks * 96;

    // ---- stage B (W1 bf16 slice) via cp.async, swizzled 16B chunks ----
    {
#pragma unroll
        for (int i = 0; i < 12; i++) {
            int c = tid + 128 * i;                 // 1536 chunks
            int row = c >> 4, nc = c & 15;
            int csw = (nc & 8) | ((nc ^ row) & 7);
            cp_async16(smem + 8192 + row * 256 + csw * 16,
                       g_w1b + (size_t)(k0 + row) * 256 + nc * 16);
        }
        asm volatile("cp.async.commit_group;" ::: "memory");
    }
    // ---- stage A (x slice), fp32 -> bf16 pack, swizzled STS.128 ----
    {
#pragma unroll
        for (int i = 0; i < 3; i++) {
            int c = tid + 128 * i;                 // 384 chunks
            int row = c / 12, kc = c % 12;
            const float* xr = x + (size_t)(row0 + row) * 768 + k0 + kc * 8;
            float4 v0 = *(const float4*)xr;
            float4 v1 = *(const float4*)(xr + 4);
            uint4 p;
            p.x = packbf2(v0.x, v0.y); p.y = packbf2(v0.z, v0.w);
            p.z = packbf2(v1.x, v1.y); p.w = packbf2(v1.z, v1.w);
            int csw = (kc & 8) | ((kc ^ row) & 7);
            *(uint4*)(smem + row * 256 + csw * 16) = p;
        }
    }
    asm volatile("cp.async.wait_group 0;" ::: "memory");
    __syncthreads();

    const int mw = warp & 1;
    const int nw = warp >> 1;

    const int arow = mw * 16 + (lane & 15);           // A row
    const uint32_t a_rowaddr = sbase + arow * 256;
    const int ar7 = arow & 7;
    const int brow_in16 = lane & 15;
    const int bhi = lane >> 4;

    float d[8][4];
#pragma unroll
    for (int t = 0; t < 8; t++)
#pragma unroll
        for (int j = 0; j < 4; j++) d[t][j] = 0.0f;

#pragma unroll
    for (int kb = 0; kb < 6; kb++) {
        uint32_t a0, a1, a2, a3;
        {
            int chunk = kb * 2 + bhi;                 // 0..11
            int csw = (chunk & 8) | ((chunk ^ ar7) & 7);
            ldsm_x4(a0, a1, a2, a3, a_rowaddr + csw * 16);
        }
        int brow = kb * 16 + brow_in16;               // 0..95
        uint32_t b_rowaddr = sbase + 8192 + brow * 256;
        int br7 = brow & 7;
#pragma unroll
        for (int ntp = 0; ntp < 4; ntp++) {
            uint32_t b0, b1, b2, b3;
            int chunk = nw * 8 + ntp * 2 + bhi;       // 0..15
            int csw = (chunk & 8) | ((chunk ^ br7) & 7);
            ldsm_x4t(b0, b1, b2, b3, b_rowaddr + csw * 16);
            mma_bf16(d[2 * ntp],     a0, a1, a2, a3, b0, b1);
            mma_bf16(d[2 * ntp + 1], a0, a1, a2, a3, b2, b3);
        }
    }

    // ---- epilogue: write partial h ----
    float* hp = g_hp + (size_t)ks * 4096 * 128 +
                (size_t)(row0 + mw * 16 + (lane >> 2)) * 128;
#pragma unroll
    for (int nt = 0; nt < 8; nt++) {
        int col = nw * 64 + nt * 8 + 2 * (lane & 3);
        *(float2*)(hp + col) = make_float2(d[nt][0], d[nt][1]);
        *(float2*)(hp + 8 * 128 + col) = make_float2(d[nt][2], d[nt][3]);
    }
}

// ---------------- kernel 1b: combine 8 partials + RoPE + bias ---------------
__global__ __launch_bounds__(256) void k1b_kernel(
    const float* __restrict__ b1, const float* __restrict__ W2,
    const float* __restrict__ b2) {
    __shared__ float h_s[32 * 133];
    __shared__ float invf_s[32];

    const int tid = threadIdx.x;
    const int tn = tid & 31;
    const int tm = tid >> 5;
    const int row0 = blockIdx.x * 32;
    const int b = row0 >> 10;

    if (tid < 32) {
        invf_s[tid] = (float)exp(-(double)tid * (9.210340371976184 / 32.0));
    }
    __syncthreads();

    const int ie = (2 * tn) & 31;
    const int io = (2 * tn + 1) & 31;
    const float invfe = invf_s[ie];
    const float invfo = invf_s[io];
    float* qTe = g_qT + (size_t)(b * 64 + 2 * tn) * 1024;
    float* qTo = qTe + 1024;
    float* kTe = g_kT + (size_t)(b * 64 + 2 * tn) * 1024;
    float* kTo = kTe + 1024;

    float4 b1v = *(const float4*)(b1 + 4 * tn);
    const size_t SPLIT = (size_t)4096 * 128;

#pragma unroll
    for (int mi = 0; mi < 4; mi++) {
        int r = 4 * tm + mi;
        int rg = row0 + r;
        int s = rg & 1023;
        size_t base = (size_t)rg * 128 + 4 * tn;
        float4 u0 = *(const float4*)(g_hp + base);
        float4 u1 = *(const float4*)(g_hp + SPLIT + base);
        float4 u2 = *(const float4*)(g_hp + 2 * SPLIT + base);
        float4 u3 = *(const float4*)(g_hp + 3 * SPLIT + base);
        float4 u4 = *(const float4*)(g_hp + 4 * SPLIT + base);
        float4 u5 = *(const float4*)(g_hp + 5 * SPLIT + base);
        float4 u6 = *(const float4*)(g_hp + 6 * SPLIT + base);
        float4 u7 = *(const float4*)(g_hp + 7 * SPLIT + base);
        float h0 = (((u0.x + u1.x) + (u2.x + u3.x)) + ((u4.x + u5.x) + (u6.x + u7.x))) + b1v.x;
        float h1 = (((u0.y + u1.y) + (u2.y + u3.y)) + ((u4.y + u5.y) + (u6.y + u7.y))) + b1v.y;
        float h2 = (((u0.z + u1.z) + (u2.z + u3.z)) + ((u4.z + u5.z) + (u6.z + u7.z))) + b1v.z;
        float h3 = (((u0.w + u1.w) + (u2.w + u3.w)) + ((u4.w + u5.w) + (u6.w + u7.w))) + b1v.w;

        h_s[r * 133 + 4 * tn + 0] = h0;
        h_s[r * 133 + 4 * tn + 1] = h1;
        h_s[r * 133 + 4 * tn + 2] = h2;
        h_s[r * 133 + 4 * tn + 3] = h3;

        float fs = (float)s;
        float se, ce, so, co;
        sincosf(fs * invfe, &se, &ce);
        sincosf(fs * invfo, &so, &co);

        qTe[s] = (h0 * ce - h2 * se) * 0.125f;
        qTo[s] = (h2 * co + h0 * so) * 0.125f;
        kTe[s] = h1 * ce - h3 * se;
        kTo[s] = h3 * co + h1 * so;
    }
    __syncthreads();

    {
        const int r = tid & 31;
        const int hb4 = (tid >> 5) * 4;
        float4 accb = *(const float4*)(b2 + hb4);
        const float* hp = h_s + r * 133;
#pragma unroll 8
        for (int kk = 0; kk < 128; kk++) {
            float hv = hp[kk];
            float4 wv = *(const float4*)(W2 + kk * 32 + hb4);
            accb.x += hv * wv.x;
            accb.y += hv * wv.y;
            accb.z += hv * wv.z;
            accb.w += hv * wv.w;
        }
        int s = (row0 & 1023) + r;
        float vals[4] = {accb.x * 0.5f, accb.y * 0.5f, accb.z * 0.5f, accb.w * 0.5f};
#pragma unroll
        for (int j = 0; j < 4; j++) {
            int ho = hb4 + j;
            int o = ho >> 1;
            if (ho & 1) g_bB[(size_t)(b * 16 + o) * 1024 + s] = vals[j];
            else        g_bA[(size_t)(b * 16 + o) * 1024 + s] = vals[j];
        }
    }
}

// ---------------- kernel 2: logits (k-tile chunked -> 34KB smem) ------------
__global__ __launch_bounds__(256) void k2_kernel(const float* __restrict__ mask,
                                                 float* __restrict__ out) {
    __shared__ __align__(16) float q_s[64 * 32];    // [d][m]   8KB (full)
    __shared__ __align__(16) float k_s[32 * 128];   // [d-chunk][n] 16KB
    __shared__ __align__(16) float bA_s[16 * 128];  // [o][n]   8KB
    __shared__ __align__(16) float bB_s[16 * 32];   // [o][m]   2KB

    const int tid = threadIdx.x;
    const int tn = tid & 31;
    const int tm = tid >> 5;
    const int b = blockIdx.z;
    const int m0 = blockIdx.y * 32;
    const int n0 = blockIdx.x * 128;

    // stage q tile [64 d][32 m] (full)
    {
        const float* src = g_qT + (size_t)b * 65536 + m0;
#pragma unroll
        for (int i = 0; i < 2; i++) {
            int f = tid + 256 * i;
            int kk = f >> 3, col = (f & 7) * 4;
            *(float4*)&q_s[kk * 32 + col] = *(const float4*)(src + kk * 1024 + col);
        }
    }
    // stage k chunk 0 [32 d][128 n]
    {
        const float* src = g_kT + (size_t)b * 65536 + n0;
#pragma unroll
        for (int i = 0; i < 4; i++) {
            int f = tid + 256 * i;
            int kk = f >> 5, col = (f & 31) * 4;
            *(float4*)&k_s[kk * 128 + col] = *(const float4*)(src + kk * 1024 + col);
        }
    }
    // stage bias tiles
    {
        const float* bAg = g_bA + (size_t)(b * 16) * 1024 + n0;
#pragma unroll
        for (int i = 0; i < 2; i++) {
            int f = tid + 256 * i;
            int o = f >> 5, col = (f & 31) * 4;
            *(float4*)&bA_s[o * 128 + col] = *(const float4*)(bAg + o * 1024 + col);
        }
        if (tid < 128) {
            const float* bBg = g_bB + (size_t)(b * 16) * 1024 + m0;
            int o = tid >> 3, col = (tid & 7) * 4;
            *(float4*)&bB_s[o * 32 + col] = *(const float4*)(bBg + o * 1024 + col);
        }
    }
    __syncthreads();

    unsigned long long acc2[4][2];
#pragma unroll
    for (int mi = 0; mi < 4; mi++) { acc2[mi][0] = 0ULL; acc2[mi][1] = 0ULL; }

    // dot chunk 0 (d = 0..31)
#pragma unroll 16
    for (int kk = 0; kk < 32; kk++) {
        float4 av = *(const float4*)&q_s[kk * 32 + 4 * tm];
        ulonglong2 bv = *(const ulonglong2*)&k_s[kk * 128 + 4 * tn];
        unsigned long long am;
        am = pk2(av.x, av.x); fma2(acc2[0][0], am, bv.x); fma2(acc2[0][1], am, bv.y);
        am = pk2(av.y, av.y); fma2(acc2[1][0], am, bv.x); fma2(acc2[1][1], am, bv.y);
        am = pk2(av.z, av.z); fma2(acc2[2][0], am, bv.x); fma2(acc2[2][1], am, bv.y);
        am = pk2(av.w, av.w); fma2(acc2[3][0], am, bv.x); fma2(acc2[3][1], am, bv.y);
    }
    __syncthreads();
    // stage k chunk 1 (d = 32..63)
    {
        const float* src = g_kT + (size_t)b * 65536 + (size_t)32 * 1024 + n0;
#pragma unroll
        for (int i = 0; i < 4; i++) {
            int f = tid + 256 * i;
            int kk = f >> 5, col = (f & 31) * 4;
            *(float4*)&k_s[kk * 128 + col] = *(const float4*)(src + kk * 1024 + col);
        }
    }
    __syncthreads();
    // dot chunk 1
#pragma unroll 16
    for (int kk = 0; kk < 32; kk++) {
        float4 av = *(const float4*)&q_s[(32 + kk) * 32 + 4 * tm];
        ulonglong2 bv = *(const ulonglong2*)&k_s[kk * 128 + 4 * tn];
        unsigned long long am;
        am = pk2(av.x, av.x); fma2(acc2[0][0], am, bv.x); fma2(acc2[0][1], am, bv.y);
        am = pk2(av.y, av.y); fma2(acc2[1][0], am, bv.x); fma2(acc2[1][1], am, bv.y);
        am = pk2(av.z, av.z); fma2(acc2[2][0], am, bv.x); fma2(acc2[2][1], am, bv.y);
        am = pk2(av.w, av.w); fma2(acc2[3][0], am, bv.x); fma2(acc2[3][1], am, bv.y);
    }

    const int nbase = n0 + 4 * tn;
    const int mbase = m0 + 4 * tm;

    float pm[4];
    {
        float4 mv = *(const float4*)(mask + b * 1024 + nbase);
        pm[0] = mv.x; pm[1] = mv.y; pm[2] = mv.z; pm[3] = mv.w;
    }
    unsigned long long pm2[2] = {pk2(pm[0], pm[1]), pk2(pm[2], pm[3])};

    unsigned long long dpm2[4][2];
#pragma unroll
    for (int mi = 0; mi < 4; mi++) {
        float2 u0 = up2(acc2[mi][0]);
        float2 u1 = up2(acc2[mi][1]);
        int mg = mbase + mi;
        float c0 = -(1.0f - pm[0]) * NEGV - (mg > nbase + 0 ? NEGV : 0.0f);
        float c1 = -(1.0f - pm[1]) * NEGV - (mg > nbase + 1 ? NEGV : 0.0f);
        float c2 = -(1.0f - pm[2]) * NEGV - (mg > nbase + 2 ? NEGV : 0.0f);
        float c3 = -(1.0f - pm[3]) * NEGV - (mg > nbase + 3 ? NEGV : 0.0f);
        dpm2[mi][0] = pk2(fmaf(u0.x, pm[0], c0), fmaf(u0.y, pm[1], c1));
        dpm2[mi][1] = pk2(fmaf(u1.x, pm[2], c2), fmaf(u1.y, pm[3], c3));
    }

    float* op0 = out + ((size_t)(b * 16) * 1024 + mbase) * 1024 + nbase;

#pragma unroll 4
    for (int o = 0; o < 16; o++) {
        float4 ba = *(const float4*)&bA_s[o * 128 + 4 * tn];
        float4 bb = *(const float4*)&bB_s[o * 32 + 4 * tm];
        unsigned long long ba2[2] = {pk2(ba.x, ba.y), pk2(ba.z, ba.w)};
        float bbv[4] = {bb.x, bb.y, bb.z, bb.w};
        float* op = op0 + (size_t)o * 1024 * 1024;
#pragma unroll
        for (int mi = 0; mi < 4; mi++) {
            unsigned long long bb2 = pk2(bbv[mi], bbv[mi]);
            unsigned long long v0 = fma2n(add2(ba2[0], bb2), pm2[0], dpm2[mi][0]);
            unsigned long long v1 = fma2n(add2(ba2[1], bb2), pm2[1], dpm2[mi][1]);
            float2 r0 = up2(v0);
            float2 r1 = up2(v1);
            float4 r = make_float4(r0.x, r0.y, r1.x, r1.y);
            __stcs((float4*)(op + (size_t)mi * 1024), r);
        }
    }
}

extern "C" void kernel_launch(void* const* d_in, const int* in_sizes, int n_in,
                              void* d_out, int out_size) {
    const float* x    = (const float*)d_in[0];  // (4,1024,768)
    const float* mask = (const float*)d_in[1];  // (4,1024)
    const float* W1   = (const float*)d_in[2];  // (768,128)
    const float* b1   = (const float*)d_in[3];  // (128)
    const float* W2   = (const float*)d_in[4];  // (128,32)
    const float* b2   = (const float*)d_in[5];  // (32)
    float* out = (float*)d_out;                 // (4,16,1024,1024)

    prep_w1_kernel<<<96, 256>>>(W1);
    k1a_kernel<<<dim3(8, 128), 128>>>(x);
    k1b_kernel<<<128, 256>>>(b1, W2, b2);
    k2_kernel<<<dim3(8, 32, 4), 256>>>(mask, out);
}

// round 11
// speedup vs baseline: 1.2025x; 1.2025x over previous
#include <cuda_runtime.h>
#include <cuda_bf16.h>
#include <cstdint>
#include <math.h>

#define NEGV 1000000000000.0f

// ---------------- scratch (static device globals; no allocs) ----------------
__device__ __align__(16) unsigned char g_w1b[768 * 128 * 2];  // W1 bf16 row-major
__device__ float g_qT[4 * 64 * 1024];    // rope'd q, TRANSPOSED [b][d][m], pre-scaled 1/8
__device__ float g_kT[4 * 64 * 1024];    // rope'd k, TRANSPOSED [b][d][n]
__device__ float g_bA[4 * 16 * 1024];    // bias[b, n, 2o]/2   -> indexed [b][o][n]
__device__ float g_bB[4 * 16 * 1024];    // bias[b, m, 2o+1]/2 -> indexed [b][o][m]

// ---------------- packed f32x2 helpers ----------------
__device__ __forceinline__ unsigned long long pk2(float lo, float hi) {
    unsigned long long r;
    asm("mov.b64 %0, {%1,%2};" : "=l"(r) : "f"(lo), "f"(hi));
    return r;
}
__device__ __forceinline__ void fma2(unsigned long long& d, unsigned long long a,
                                     unsigned long long b) {
    asm("fma.rn.f32x2 %0, %1, %2, %0;" : "+l"(d) : "l"(a), "l"(b));
}
__device__ __forceinline__ unsigned long long fma2n(unsigned long long a,
                                                    unsigned long long b,
                                                    unsigned long long c) {
    unsigned long long d;
    asm("fma.rn.f32x2 %0, %1, %2, %3;" : "=l"(d) : "l"(a), "l"(b), "l"(c));
    return d;
}
__device__ __forceinline__ unsigned long long add2(unsigned long long a,
                                                   unsigned long long b) {
    unsigned long long d;
    asm("add.rn.f32x2 %0, %1, %2;" : "=l"(d) : "l"(a), "l"(b));
    return d;
}
__device__ __forceinline__ float2 up2(unsigned long long v) {
    float2 r;
    asm("mov.b64 {%0,%1}, %2;" : "=f"(r.x), "=f"(r.y) : "l"(v));
    return r;
}
__device__ __forceinline__ void cp_async16(void* smem_dst, const void* gsrc) {
    unsigned saddr = (unsigned)__cvta_generic_to_shared(smem_dst);
    asm volatile("cp.async.ca.shared.global [%0], [%1], 16;\n"
                 :: "r"(saddr), "l"(gsrc) : "memory");
}
__device__ __forceinline__ uint32_t packbf2(float a, float b) {
    __nv_bfloat162 v = __floats2bfloat162_rn(a, b);
    return *(uint32_t*)&v;
}
__device__ __forceinline__ void ldsm_x4(uint32_t& r0, uint32_t& r1, uint32_t& r2,
                                        uint32_t& r3, uint32_t addr) {
    asm volatile("ldmatrix.sync.aligned.m8n8.x4.shared.b16 {%0,%1,%2,%3}, [%4];"
                 : "=r"(r0), "=r"(r1), "=r"(r2), "=r"(r3) : "r"(addr));
}
__device__ __forceinline__ void ldsm_x4t(uint32_t& r0, uint32_t& r1, uint32_t& r2,
                                         uint32_t& r3, uint32_t addr) {
    asm volatile("ldmatrix.sync.aligned.m8n8.x4.trans.shared.b16 {%0,%1,%2,%3}, [%4];"
                 : "=r"(r0), "=r"(r1), "=r"(r2), "=r"(r3) : "r"(addr));
}
__device__ __forceinline__ void mma_bf16(float* d, uint32_t a0, uint32_t a1,
                                         uint32_t a2, uint32_t a3, uint32_t b0,
                                         uint32_t b1) {
    asm volatile(
        "mma.sync.aligned.m16n8k16.row.col.f32.bf16.bf16.f32 "
        "{%0,%1,%2,%3}, {%4,%5,%6,%7}, {%8,%9}, {%0,%1,%2,%3};"
        : "+f"(d[0]), "+f"(d[1]), "+f"(d[2]), "+f"(d[3])
        : "r"(a0), "r"(a1), "r"(a2), "r"(a3), "r"(b0), "r"(b1));
}

// ---------------- prep: W1 -> bf16 row-major ----------------
__global__ __launch_bounds__(256) void prep_w1_kernel(const float* __restrict__ W1) {
    int i = (blockIdx.x * 256 + threadIdx.x) * 4;   // 98304 elements
    float4 v = *(const float4*)(W1 + i);
    uint2 p;
    p.x = packbf2(v.x, v.y);
    p.y = packbf2(v.z, v.w);
    *(uint2*)(g_w1b + (size_t)i * 2) = p;
}

// ---------------- kernel 1 (fused): h = x@W1+b1 -> RoPE qT/kT + bias --------
// 128 blocks (32 rows), 256 thr (8 warps). Full K=768 in 12 double-buffered
// BK=64 stages. Warp = m16 x n32 tile. No g_hp round trip.
// smem: A bufs @0 (2x4KB), B bufs @8192 (2x16KB), b1s @40960, invf @41472.
// h tile (32x133 fp32, 17KB) reuses the A/B region after the MMA loop.
__global__ __launch_bounds__(256) void k1_kernel(
    const float* __restrict__ x, const float* __restrict__ b1,
    const float* __restrict__ W2, const float* __restrict__ b2) {
    __shared__ __align__(16) unsigned char smem[41600];
    const uint32_t sbase = (uint32_t)__cvta_generic_to_shared(smem);
    float* b1s = (float*)(smem + 40960);
    float* invf_s = (float*)(smem + 41472);

    const int tid = threadIdx.x;
    const int lane = tid & 31;
    const int warp = tid >> 5;
    const int row0 = blockIdx.x * 32;

    if (tid < 128) b1s[tid] = b1[tid];
    else if (tid < 160) {
        int j = tid - 128;
        invf_s[j] = (float)exp(-(double)j * (9.210340371976184 / 32.0));
    }

    // A staging map: thread -> one 16B chunk (8 bf16) of the 32x64 tile
    const int As_row = tid >> 3;       // 0..31
    const int As_kc = tid & 7;         // 0..7
    const int As_csw = (As_kc ^ (As_row & 7)) & 7;
    const float* xr = x + (size_t)(row0 + As_row) * 768 + As_kc * 8;

    // ---- prologue: stage kt=0 ----
    {
#pragma unroll
        for (int i = 0; i < 4; i++) {
            int c = tid + 256 * i;             // 1024 chunks
            int row = c >> 4, nc = c & 15;
            int csw = (nc & 8) | ((nc ^ row) & 7);
            cp_async16(smem + 8192 + row * 256 + csw * 16,
                       g_w1b + (size_t)row * 256 + nc * 16);
        }
        asm volatile("cp.async.commit_group;" ::: "memory");
        float4 v0 = *(const float4*)xr;
        float4 v1 = *(const float4*)(xr + 4);
        uint4 p;
        p.x = packbf2(v0.x, v0.y); p.y = packbf2(v0.z, v0.w);
        p.z = packbf2(v1.x, v1.y); p.w = packbf2(v1.z, v1.w);
        *(uint4*)(smem + As_row * 128 + As_csw * 16) = p;
        asm volatile("cp.async.wait_group 0;" ::: "memory");
        __syncthreads();
    }

    const int mw = warp & 1;           // m16 tile
    const int nv = warp >> 1;          // n32 group (0..3)
    const int arow = mw * 16 + (lane & 15);
    const int ar7 = arow & 7;
    const int brow16 = lane & 15;
    const int bhi = lane >> 4;

    float d[4][4];
#pragma unroll
    for (int t = 0; t < 4; t++)
#pragma unroll
        for (int j = 0; j < 4; j++) d[t][j] = 0.0f;

    float4 pv0, pv1;
    for (int kt = 0; kt < 12; kt++) {
        const uint32_t abuf = (kt & 1) * 4096;
        const uint32_t bbuf = 8192 + (kt & 1) * 16384;

        if (kt < 11) {
            // issue B(kt+1) + LDG A(kt+1)
            const unsigned char* wb = g_w1b + (size_t)(kt + 1) * 64 * 256;
            unsigned char* bd = smem + 8192 + ((kt + 1) & 1) * 16384;
#pragma unroll
            for (int i = 0; i < 4; i++) {
                int c = tid + 256 * i;
                int row = c >> 4, nc = c & 15;
                int csw = (nc & 8) | ((nc ^ row) & 7);
                cp_async16(bd + row * 256 + csw * 16,
                           wb + (size_t)row * 256 + nc * 16);
            }
            asm volatile("cp.async.commit_group;" ::: "memory");
            pv0 = *(const float4*)(xr + (kt + 1) * 64);
            pv1 = *(const float4*)(xr + (kt + 1) * 64 + 4);
        }

        // compute kt
#pragma unroll
        for (int ks = 0; ks < 4; ks++) {
            uint32_t a0, a1, a2, a3;
            {
                int chunk = ks * 2 + bhi;
                int csw = (chunk ^ ar7) & 7;
                ldsm_x4(a0, a1, a2, a3, sbase + abuf + arow * 128 + csw * 16);
            }
            int brow = ks * 16 + brow16;
            uint32_t braddr = sbase + bbuf + brow * 256;
            int br7 = brow & 7;
#pragma unroll
            for (int ntp = 0; ntp < 2; ntp++) {
                uint32_t b0, b1r, b2, b3;
                int chunk = nv * 4 + ntp * 2 + bhi;
                int csw = (chunk & 8) | ((chunk ^ br7) & 7);
                ldsm_x4t(b0, b1r, b2, b3, braddr + csw * 16);
                mma_bf16(d[2 * ntp],     a0, a1, a2, a3, b0, b1r);
                mma_bf16(d[2 * ntp + 1], a0, a1, a2, a3, b2, b3);
            }
        }

        if (kt < 11) {
            // STS A(kt+1) into other buffer
            uint4 p;
            p.x = packbf2(pv0.x, pv0.y); p.y = packbf2(pv0.z, pv0.w);
            p.z = packbf2(pv1.x, pv1.y); p.w = packbf2(pv1.z, pv1.w);
            *(uint4*)(smem + (((kt + 1) & 1) * 4096) + As_row * 128 + As_csw * 16) = p;
            asm volatile("cp.async.wait_group 0;" ::: "memory");
            __syncthreads();
        }
    }
    __syncthreads();   // all warps done with A/B smem

    // ---- acc(+b1) -> h tile in smem (reuse A/B region) ----
    float* h_s = (float*)smem;
    {
        int r = mw * 16 + (lane >> 2);
#pragma unroll
        for (int nt = 0; nt < 4; nt++) {
            int col = nv * 32 + nt * 8 + 2 * (lane & 3);
            h_s[r * 133 + col]           = d[nt][0] + b1s[col];
            h_s[r * 133 + col + 1]       = d[nt][1] + b1s[col + 1];
            h_s[(r + 8) * 133 + col]     = d[nt][2] + b1s[col];
            h_s[(r + 8) * 133 + col + 1] = d[nt][3] + b1s[col + 1];
        }
    }
    __syncthreads();

    // ---- RoPE -> qT/kT ----
    const int tn = tid & 31;
    const int tmw = tid >> 5;
    const int b = row0 >> 10;
    const float invfe = invf_s[(2 * tn) & 31];
    const float invfo = invf_s[(2 * tn + 1) & 31];
    float* qTe = g_qT + (size_t)(b * 64 + 2 * tn) * 1024;
    float* qTo = qTe + 1024;
    float* kTe = g_kT + (size_t)(b * 64 + 2 * tn) * 1024;
    float* kTo = kTe + 1024;

#pragma unroll
    for (int mi = 0; mi < 4; mi++) {
        int r = 4 * tmw + mi;
        int s = (row0 & 1023) + r;
        float h0 = h_s[r * 133 + 4 * tn + 0];
        float h1 = h_s[r * 133 + 4 * tn + 1];
        float h2 = h_s[r * 133 + 4 * tn + 2];
        float h3 = h_s[r * 133 + 4 * tn + 3];

        float fs = (float)s;
        float se, ce, so, co;
        sincosf(fs * invfe, &se, &ce);
        sincosf(fs * invfo, &so, &co);

        qTe[s] = (h0 * ce - h2 * se) * 0.125f;
        qTo[s] = (h2 * co + h0 * so) * 0.125f;
        kTe[s] = h1 * ce - h3 * se;
        kTo[s] = h3 * co + h1 * so;
    }

    // ---- bias GEMM: h @ W2 + b2 ----
    {
        const int r = tid & 31;
        const int hb4 = (tid >> 5) * 4;
        float4 accb = *(const float4*)(b2 + hb4);
        const float* hp = h_s + r * 133;
#pragma unroll 8
        for (int kk = 0; kk < 128; kk++) {
            float hv = hp[kk];
            float4 wv = *(const float4*)(W2 + kk * 32 + hb4);
            accb.x += hv * wv.x;
            accb.y += hv * wv.y;
            accb.z += hv * wv.z;
            accb.w += hv * wv.w;
        }
        int s = (row0 & 1023) + r;
        float vals[4] = {accb.x * 0.5f, accb.y * 0.5f, accb.z * 0.5f, accb.w * 0.5f};
#pragma unroll
        for (int j = 0; j < 4; j++) {
            int ho = hb4 + j;
            int o = ho >> 1;
            if (ho & 1) g_bB[(size_t)(b * 16 + o) * 1024 + s] = vals[j];
            else        g_bA[(size_t)(b * 16 + o) * 1024 + s] = vals[j];
        }
    }
}

// ---------------- kernel 2: logits (R8 version — best known, 46.0us) --------
__global__ __launch_bounds__(256) void k2_kernel(const float* __restrict__ mask,
                                                 float* __restrict__ out) {
    __shared__ __align__(16) float q_s[64 * 32];    // [k][m]   8KB
    __shared__ __align__(16) float k_s[64 * 128];   // [k][n]  32KB
    __shared__ __align__(16) float bA_s[16 * 128];  // [o][n]   8KB
    __shared__ __align__(16) float bB_s[16 * 32];   // [o][m]   2KB

    const int tid = threadIdx.x;
    const int tn = tid & 31;
    const int tm = tid >> 5;
    const int b = blockIdx.z;
    const int m0 = blockIdx.y * 32;
    const int n0 = blockIdx.x * 128;

    {
        const float* src = g_qT + (size_t)b * 65536 + m0;
#pragma unroll
        for (int i = 0; i < 2; i++) {
            int f = tid + 256 * i;
            int kk = f >> 3, col = (f & 7) * 4;
            *(float4*)&q_s[kk * 32 + col] = *(const float4*)(src + kk * 1024 + col);
        }
    }
    {
        const float* src = g_kT + (size_t)b * 65536 + n0;
#pragma unroll
        for (int i = 0; i < 8; i++) {
            int f = tid + 256 * i;
            int kk = f >> 5, col = (f & 31) * 4;
            *(float4*)&k_s[kk * 128 + col] = *(const float4*)(src + kk * 1024 + col);
        }
    }
    {
        const float* bAg = g_bA + (size_t)(b * 16) * 1024 + n0;
#pragma unroll
        for (int i = 0; i < 2; i++) {
            int f = tid + 256 * i;
            int o = f >> 5, col = (f & 31) * 4;
            *(float4*)&bA_s[o * 128 + col] = *(const float4*)(bAg + o * 1024 + col);
        }
        if (tid < 128) {
            const float* bBg = g_bB + (size_t)(b * 16) * 1024 + m0;
            int o = tid >> 3, col = (tid & 7) * 4;
            *(float4*)&bB_s[o * 32 + col] = *(const float4*)(bBg + o * 1024 + col);
        }
    }
    __syncthreads();

    unsigned long long acc2[4][2];
#pragma unroll
    for (int mi = 0; mi < 4; mi++) { acc2[mi][0] = 0ULL; acc2[mi][1] = 0ULL; }

#pragma unroll 16
    for (int kk = 0; kk < 64; kk++) {
        float4 av = *(const float4*)&q_s[kk * 32 + 4 * tm];
        ulonglong2 bv = *(const ulonglong2*)&k_s[kk * 128 + 4 * tn];
        unsigned long long am;
        am = pk2(av.x, av.x); fma2(acc2[0][0], am, bv.x); fma2(acc2[0][1], am, bv.y);
        am = pk2(av.y, av.y); fma2(acc2[1][0], am, bv.x); fma2(acc2[1][1], am, bv.y);
        am = pk2(av.z, av.z); fma2(acc2[2][0], am, bv.x); fma2(acc2[2][1], am, bv.y);
        am = pk2(av.w, av.w); fma2(acc2[3][0], am, bv.x); fma2(acc2[3][1], am, bv.y);
    }

    const int nbase = n0 + 4 * tn;
    const int mbase = m0 + 4 * tm;

    float pm[4];
    {
        float4 mv = *(const float4*)(mask + b * 1024 + nbase);
        pm[0] = mv.x; pm[1] = mv.y; pm[2] = mv.z; pm[3] = mv.w;
    }
    unsigned long long pm2[2] = {pk2(pm[0], pm[1]), pk2(pm[2], pm[3])};

    unsigned long long dpm2[4][2];
#pragma unroll
    for (int mi = 0; mi < 4; mi++) {
        float2 u0 = up2(acc2[mi][0]);
        float2 u1 = up2(acc2[mi][1]);
        int mg = mbase + mi;
        float c0 = -(1.0f - pm[0]) * NEGV - (mg > nbase + 0 ? NEGV : 0.0f);
        float c1 = -(1.0f - pm[1]) * NEGV - (mg > nbase + 1 ? NEGV : 0.0f);
        float c2 = -(1.0f - pm[2]) * NEGV - (mg > nbase + 2 ? NEGV : 0.0f);
        float c3 = -(1.0f - pm[3]) * NEGV - (mg > nbase + 3 ? NEGV : 0.0f);
        dpm2[mi][0] = pk2(fmaf(u0.x, pm[0], c0), fmaf(u0.y, pm[1], c1));
        dpm2[mi][1] = pk2(fmaf(u1.x, pm[2], c2), fmaf(u1.y, pm[3], c3));
    }

    float* op0 = out + ((size_t)(b * 16) * 1024 + mbase) * 1024 + nbase;

#pragma unroll 4
    for (int o = 0; o < 16; o++) {
        float4 ba = *(const float4*)&bA_s[o * 128 + 4 * tn];
        float4 bb = *(const float4*)&bB_s[o * 32 + 4 * tm];
        unsigned long long ba2[2] = {pk2(ba.x, ba.y), pk2(ba.z, ba.w)};
        float bbv[4] = {bb.x, bb.y, bb.z, bb.w};
        float* op = op0 + (size_t)o * 1024 * 1024;
#pragma unroll
        for (int mi = 0; mi < 4; mi++) {
            unsigned long long bb2 = pk2(bbv[mi], bbv[mi]);
            unsigned long long v0 = fma2n(add2(ba2[0], bb2), pm2[0], dpm2[mi][0]);
            unsigned long long v1 = fma2n(add2(ba2[1], bb2), pm2[1], dpm2[mi][1]);
            float2 r0 = up2(v0);
            float2 r1 = up2(v1);
            float4 r = make_float4(r0.x, r0.y, r1.x, r1.y);
            __stcs((float4*)(op + (size_t)mi * 1024), r);
        }
    }
}

extern "C" void kernel_launch(void* const* d_in, const int* in_sizes, int n_in,
                              void* d_out, int out_size) {
    const float* x    = (const float*)d_in[0];  // (4,1024,768)
    const float* mask = (const float*)d_in[1];  // (4,1024)
    const float* W1   = (const float*)d_in[2];  // (768,128)
    const float* b1   = (const float*)d_in[3];  // (128)
    const float* W2   = (const float*)d_in[4];  // (128,32)
    const float* b2   = (const float*)d_in[5];  // (32)
    float* out = (float*)d_out;                 // (4,16,1024,1024)

    prep_w1_kernel<<<96, 256>>>(W1);
    k1_kernel<<<128, 256>>>(x, b1, W2, b2);
    k2_kernel<<<dim3(8, 32, 4), 256>>>(mask, out);
}